// round 14
// baseline (speedup 1.0000x reference)
#include <cuda_runtime.h>
#include <cuda_fp16.h>
#include <cstdint>

// Problem constants (B=2, S=1024, H=32, KVH=8, HD=128, DM=4096)
#define T_TOK   2048
#define DMODEL  4096
#define QKVC    6144
#define NH      32
#define NKV     8
#define HDIM    128
#define SEQ     1024
#define NBATCH  2
#define QSCALE  0.08838834764831845f

__device__ uint32_t g_qkvh[(size_t)T_TOK * QKVC / 2];      // GEMM output, fp16 half2
__device__ uint32_t g_pa[(size_t)T_TOK * DMODEL / 2];      // packed fp16 A tiles (GEMM)
__device__ uint32_t g_pb[(size_t)QKVC * DMODEL / 2];       // packed fp16 W tiles (GEMM)
__device__ uint32_t g_pq[(size_t)T_TOK * NH * HDIM / 2];   // Q A-frag tiles (post-rope)
__device__ uint32_t g_pk[(size_t)T_TOK * NKV * HDIM / 2];  // K B-frag tiles (post-rope)
__device__ uint32_t g_pv[(size_t)T_TOK * NKV * HDIM / 2];  // V B-frag tiles (transposed)

__device__ __forceinline__ uint32_t pack_h2(float lo, float hi) {
    __half2 h = __floats2half2_rn(lo, hi);
    return *reinterpret_cast<uint32_t*>(&h);
}
__device__ __forceinline__ float2 unpack_h2(uint32_t u) {
    __half2 h = *reinterpret_cast<__half2*>(&u);
    return __half22float2(h);
}

#define MMA_F16(d, a, b)                                                      \
    asm volatile(                                                             \
        "mma.sync.aligned.m16n8k16.row.col.f32.f16.f16.f32 "                  \
        "{%0,%1,%2,%3},{%4,%5,%6,%7},{%8,%9},{%0,%1,%2,%3};"                  \
        : "+f"(d[0]), "+f"(d[1]), "+f"(d[2]), "+f"(d[3])                      \
        : "r"(a[0]), "r"(a[1]), "r"(a[2]), "r"(a[3]), "r"(b[0]), "r"(b[1]))

__device__ __forceinline__ void cp_async16(uint32_t smem_addr, const void* gptr) {
    asm volatile("cp.async.cg.shared.global [%0], [%1], 16;"
                 :: "r"(smem_addr), "l"(gptr) : "memory");
}
#define CP_COMMIT() asm volatile("cp.async.commit_group;" ::: "memory")
#define CP_WAIT1()  asm volatile("cp.async.wait_group 1;" ::: "memory")

// ---------------------------------------------------------------------------
// Kernel 0a/0b: pack A and W for the GEMM (verified layouts).
// ---------------------------------------------------------------------------
__global__ __launch_bounds__(256) void pack_a_kernel(const float* __restrict__ A) {
    int i = blockIdx.x * 256 + threadIdx.x;
    int r  = i >> 10;
    int k0 = (i & 1023) << 2;
    float4 v = *reinterpret_cast<const float4*>(A + (size_t)r * DMODEL + k0);

    int mTile = r >> 7, rLoc = r & 127;
    int kTile = k0 >> 4, kLoc = k0 & 15;
    uint32_t* dst = g_pa + ((size_t)(mTile * (DMODEL / 16) + kTile)) * 1024;

    int rb = rLoc >> 4, r16 = rLoc & 15;
    int reg = ((kLoc >= 8) ? 2 : 0) + ((r16 >= 8) ? 1 : 0);
    int lane0 = (r16 & 7) * 4 + ((kLoc >> 1) & 3);
    int base = rb * 128;
    dst[base + lane0 * 4 + reg]       = pack_h2(v.x, v.y);
    dst[base + (lane0 + 1) * 4 + reg] = pack_h2(v.z, v.w);
}

__global__ __launch_bounds__(256) void pack_w_kernel(const float* __restrict__ W) {
    int i = blockIdx.x * 256 + threadIdx.x;
    int kp = i / 1536;
    int n0 = (i - kp * 1536) << 2;
    int k  = kp * 2;
    float4 vlo = *reinterpret_cast<const float4*>(W + (size_t)k * QKVC + n0);
    float4 vhi = *reinterpret_cast<const float4*>(W + (size_t)(k + 1) * QKVC + n0);

    int nTile = n0 >> 7, nLoc0 = n0 & 127;
    int kTile = k >> 4,  kLoc  = k & 15;
    uint32_t* dst = g_pb + ((size_t)(nTile * (DMODEL / 16) + kTile)) * 1024;

    int tig = (kLoc >> 1) & 3;
    int reg = (kLoc >= 8) ? 1 : 0;
    float lo[4] = {vlo.x, vlo.y, vlo.z, vlo.w};
    float hi[4] = {vhi.x, vhi.y, vhi.z, vhi.w};
#pragma unroll
    for (int j = 0; j < 4; j++) {
        int n = nLoc0 + j;
        int nblk = n >> 3, nn = n & 7;
        dst[nblk * 64 + (nn * 4 + tig) * 2 + reg] = pack_h2(lo[j], hi[j]);
    }
}

// ---------------------------------------------------------------------------
// Kernel 1: QKV GEMM, fp16 m16n8k16, BK=64, 3 stages 96KB.
// CTA 128x128, 128 threads (4 warps as 2x2), warp tile 64x64.
// Per ktile per warp: 4 A-frags + 8 B-frags -> 32 MMAs (smem traffic/MMA -32%).
// ---------------------------------------------------------------------------
__global__ __launch_bounds__(128, 2) void gemm_f16_kernel() {
    extern __shared__ __align__(16) uint32_t smem[];

    const int tid  = threadIdx.x;
    const int wid  = tid >> 5;
    const int lane = tid & 31;
    const int gid  = lane >> 2;
    const int tig  = lane & 3;
    const int wm   = wid >> 1;        // 0..1 (M)
    const int wn   = wid & 1;         // 0..1 (N)

    const uint32_t smem_base = (uint32_t)__cvta_generic_to_shared(smem);
    const uint32_t* pa = g_pa + (size_t)blockIdx.y * (DMODEL / 16) * 1024;
    const uint32_t* pb = g_pb + (size_t)blockIdx.x * (DMODEL / 16) * 1024;

    const int NCH = DMODEL / 64;   // 64 chunks

    // Stage layout (words): [A kt0..kt3: 4096][B kt0..kt3: 4096]; 128 threads.
#define ISSUE(ch, s)                                                           \
    do {                                                                       \
        uint32_t sa = smem_base + (uint32_t)(s) * 32768;                       \
        const uint32_t* gA = pa + (size_t)(ch) * 4096 + tid * 4;               \
        const uint32_t* gB = pb + (size_t)(ch) * 4096 + tid * 4;               \
        _Pragma("unroll")                                                      \
        for (int i = 0; i < 8; i++) {                                          \
            cp_async16(sa + tid * 16 + i * 2048,         gA + i * 512);        \
            cp_async16(sa + 16384 + tid * 16 + i * 2048, gB + i * 512);        \
        }                                                                      \
    } while (0)

    float acc[4][8][4];
#pragma unroll
    for (int i = 0; i < 4; i++)
#pragma unroll
        for (int j = 0; j < 8; j++)
#pragma unroll
            for (int c = 0; c < 4; c++) acc[i][j][c] = 0.f;

    ISSUE(0, 0); CP_COMMIT();
    ISSUE(1, 1); CP_COMMIT();
    CP_WAIT1();
    __syncthreads();

    for (int ch = 0; ch < NCH; ch++) {
        if (ch + 2 < NCH) ISSUE(ch + 2, (ch + 2) % 3);
        CP_COMMIT();

        const uint32_t* St = smem + (size_t)(ch % 3) * 8192;

#pragma unroll
        for (int kt = 0; kt < 4; kt++) {
            const uint32_t* As = St + kt * 1024;
            const uint32_t* Bs = St + 4096 + kt * 1024;
            uint4 av[4];
            uint2 bv[8];
#pragma unroll
            for (int i = 0; i < 4; i++)
                av[i] = *reinterpret_cast<const uint4*>(
                    &As[((wm << 2) + i) * 128 + (lane << 2)]);
#pragma unroll
            for (int j = 0; j < 8; j++)
                bv[j] = *reinterpret_cast<const uint2*>(
                    &Bs[((wn << 3) + j) * 64 + (lane << 1)]);
#pragma unroll
            for (int i = 0; i < 4; i++)
#pragma unroll
                for (int j = 0; j < 8; j++)
                    MMA_F16(acc[i][j], (reinterpret_cast<uint32_t*>(&av[i])),
                            (reinterpret_cast<uint32_t*>(&bv[j])));
        }

        CP_WAIT1();
        __syncthreads();
    }

    // Epilogue: fp16 half2 words. Column pair index = wn*32 + j*4 + tig.
    uint32_t* C = g_qkvh + (size_t)blockIdx.y * 128 * (QKVC / 2) + blockIdx.x * 64;
#pragma unroll
    for (int i = 0; i < 4; i++) {
#pragma unroll
        for (int j = 0; j < 8; j++) {
            int r = wm * 64 + i * 16 + gid;
            int cp = wn * 32 + j * 4 + tig;
            C[(size_t)(r)     * (QKVC / 2) + cp] = pack_h2(acc[i][j][0], acc[i][j][1]);
            C[(size_t)(r + 8) * (QKVC / 2) + cp] = pack_h2(acc[i][j][2], acc[i][j][3]);
        }
    }
}

// ---------------------------------------------------------------------------
// Kernel 2 (fused): RoPE+pack Q/K, then pack V (block-range split).
// ---------------------------------------------------------------------------
#define ROPE_BLOCKS 10240   // T_TOK*40*32/256
#define PACKV_BLOCKS 1024   // (T_TOK/2)*8*32/256

__global__ __launch_bounds__(256) void rope_packqkv_kernel(const float* __restrict__ cosT,
                                                           const float* __restrict__ sinT) {
    if (blockIdx.x < ROPE_BLOCKS) {
        int idx = blockIdx.x * 256 + threadIdx.x;
        int j    = idx & 31;
        int head = (idx >> 5) % 40;
        int t    = idx / (32 * 40);
        int d0   = 2 * j;

        const uint32_t* p = g_qkvh + (size_t)t * (QKVC / 2) + head * 64;
        float2 x1 = unpack_h2(p[j]);
        float2 x2 = unpack_h2(p[32 + j]);
        float2 c  = *reinterpret_cast<const float2*>(cosT + t * HDIM + d0);
        float2 s  = *reinterpret_cast<const float2*>(sinT + t * HDIM + d0);

        float lo0 = x1.x * c.x - x2.x * s.x;
        float lo1 = x1.y * c.y - x2.y * s.y;
        float hi0 = x2.x * c.x + x1.x * s.x;
        float hi1 = x2.y * c.y + x1.y * s.y;

        int b = t >> 10;
        int tig = j & 3;
        int ktile = j >> 3;
        if (head < NH) {
            lo0 *= QSCALE; lo1 *= QSCALE; hi0 *= QSCALE; hi1 *= QSCALE;
            int qblk = (t & 1023) >> 7;
            int rLoc = t & 127, rb = rLoc >> 4, r16 = rLoc & 15;
            int reg = (((d0 & 15) >= 8) ? 2 : 0) + ((r16 >= 8) ? 1 : 0);
            int lane0 = (r16 & 7) * 4 + tig;
            uint32_t* dst = g_pq + ((size_t)((b * 8 + qblk) * 32 + head)) * 8192 + rb * 128;
            dst[ktile * 1024 + lane0 * 4 + reg]       = pack_h2(lo0, lo1);
            dst[(ktile + 4) * 1024 + lane0 * 4 + reg] = pack_h2(hi0, hi1);
        } else {
            int hkv = head - NH;
            int kvblk = (t & 1023) >> 6;
            int n = t & 63, nblk = n >> 3, nn = n & 7;
            int reg = ((d0 & 15) >= 8) ? 1 : 0;
            uint32_t* dst = g_pk + ((size_t)((b * 8 + hkv) * 16 + kvblk)) * 4096
                            + nblk * 64 + (nn * 4 + tig) * 2 + reg;
            dst[ktile * 512]       = pack_h2(lo0, lo1);
            dst[(ktile + 4) * 512] = pack_h2(hi0, hi1);
        }
    } else {
        int idx = (blockIdx.x - ROPE_BLOCKS) * 256 + threadIdx.x;
        int dq  = idx & 31;
        int hkv = (idx >> 5) & 7;
        int tp  = idx >> 8;
        int t   = tp * 2;
        int d0  = dq * 4;

        const uint32_t* Vg = g_qkvh + (size_t)t * (QKVC / 2) + (NH + NKV + hkv) * 64 + (d0 >> 1);
        uint2 vlo = *reinterpret_cast<const uint2*>(Vg);
        uint2 vhi = *reinterpret_cast<const uint2*>(Vg + (QKVC / 2));

        int b = t >> 10;
        int kvblk = (t & 1023) >> 6;
        int kc = t & 15;
        int tig = (kc >> 1) & 3;
        int reg = (kc >= 8) ? 1 : 0;
        int ktv = (t & 63) >> 4;
        uint32_t* dst = g_pv + ((size_t)((b * 8 + hkv) * 16 + kvblk)) * 4096 + ktv * 1024;

        uint32_t w[4];
        w[0] = __byte_perm(vlo.x, vhi.x, 0x5410);
        w[1] = __byte_perm(vlo.x, vhi.x, 0x7632);
        w[2] = __byte_perm(vlo.y, vhi.y, 0x5410);
        w[3] = __byte_perm(vlo.y, vhi.y, 0x7632);
#pragma unroll
        for (int jj = 0; jj < 4; jj++) {
            int d = d0 + jj;
            int nblk = d >> 3, nn = d & 7;
            dst[nblk * 64 + (nn * 4 + tig) * 2 + reg] = w[jj];
        }
    }
}

// ---------------------------------------------------------------------------
// Kernel 3: fp16 flash attention; Q and P register-resident, K/V via cp.async.
// (unchanged from R13 best)
// ---------------------------------------------------------------------------
#define ATTN_SMEM (3 * 8192 * 4)   // 98304

__global__ __launch_bounds__(256) void attn_tc_kernel(float* __restrict__ out) {
    extern __shared__ __align__(16) uint32_t sm[];
    const uint32_t smem_base = (uint32_t)__cvta_generic_to_shared(sm);

    const int tid  = threadIdx.x;
    const int wid  = tid >> 5;
    const int lane = tid & 31;
    const int gid  = lane >> 2;
    const int tig  = lane & 3;
    const int qrow = wid * 16;

    const int b   = blockIdx.y >> 5;
    const int h   = blockIdx.y & 31;
    const int kvh = h >> 2;
    const int q0  = blockIdx.x * 128;

    const uint32_t* qbase = g_pq + ((size_t)((b * 8 + blockIdx.x) * 32 + h)) * 8192;
    uint4 qa[8];
#pragma unroll
    for (int ks = 0; ks < 8; ks++)
        qa[ks] = *reinterpret_cast<const uint4*>(qbase + ks * 1024 + wid * 128 + lane * 4);

    const uint32_t* kbase = g_pk + ((size_t)((b * 8 + kvh) * 16)) * 4096;
    const uint32_t* vbase = g_pv + ((size_t)((b * 8 + kvh) * 16)) * 4096;

#define AISSUE(kt, s)                                                          \
    do {                                                                       \
        uint32_t sa = smem_base + (uint32_t)(s) * 32768;                       \
        const uint32_t* gK = kbase + (size_t)(kt) * 4096;                      \
        const uint32_t* gV = vbase + (size_t)(kt) * 4096;                      \
        _Pragma("unroll")                                                      \
        for (int i = 0; i < 4; i++) {                                          \
            int c = tid + i * 256;                                             \
            cp_async16(sa + c * 16,         gK + c * 4);                       \
            cp_async16(sa + 16384 + c * 16, gV + c * 4);                       \
        }                                                                      \
    } while (0)

    float m[2] = {-1e30f, -1e30f}, l[2] = {0.f, 0.f};
    float oacc[16][4];
#pragma unroll
    for (int nb = 0; nb < 16; nb++)
#pragma unroll
        for (int c = 0; c < 4; c++) oacc[nb][c] = 0.f;

    const int ktiles = 2 * (blockIdx.x + 1);
    AISSUE(0, 0); CP_COMMIT();
    AISSUE(1, 1); CP_COMMIT();

    for (int kt = 0; kt < ktiles; kt++) {
        const int kv0 = kt * 64;
        CP_WAIT1();
        __syncthreads();
        if (kt + 2 < ktiles) AISSUE(kt + 2, (kt + 2) % 3);
        CP_COMMIT();

        const uint32_t* Kst = sm + (size_t)(kt % 3) * 8192;
        const uint32_t* Vst = Kst + 4096;

        float sacc[8][4];
#pragma unroll
        for (int nb = 0; nb < 8; nb++)
#pragma unroll
            for (int c = 0; c < 4; c++) sacc[nb][c] = 0.f;

#pragma unroll
        for (int ks = 0; ks < 8; ks++) {
#pragma unroll
            for (int nb = 0; nb < 8; nb++) {
                uint2 bb = *reinterpret_cast<const uint2*>(
                    &Kst[ks * 512 + nb * 64 + (lane << 1)]);
                MMA_F16(sacc[nb], (reinterpret_cast<uint32_t*>(&qa[ks])),
                        (reinterpret_cast<uint32_t*>(&bb)));
            }
        }

        const int row0 = q0 + qrow + gid;
        const int row1 = row0 + 8;
        if (kv0 + 63 > row0) {
#pragma unroll
            for (int nb = 0; nb < 8; nb++) {
                int c0 = kv0 + nb * 8 + 2 * tig;
                if (c0 > row0)     sacc[nb][0] = -1e30f;
                if (c0 + 1 > row0) sacc[nb][1] = -1e30f;
                if (c0 > row1)     sacc[nb][2] = -1e30f;
                if (c0 + 1 > row1) sacc[nb][3] = -1e30f;
            }
        }

#pragma unroll
        for (int r = 0; r < 2; r++) {
            float rmax = -1e30f;
#pragma unroll
            for (int nb = 0; nb < 8; nb++)
                rmax = fmaxf(rmax, fmaxf(sacc[nb][2 * r], sacc[nb][2 * r + 1]));
            rmax = fmaxf(rmax, __shfl_xor_sync(0xffffffffu, rmax, 1));
            rmax = fmaxf(rmax, __shfl_xor_sync(0xffffffffu, rmax, 2));
            float nm = fmaxf(m[r], rmax);
            float corr = __expf(m[r] - nm);
            float rs = 0.f;
#pragma unroll
            for (int nb = 0; nb < 8; nb++) {
                float p0 = __expf(sacc[nb][2 * r]     - nm);
                float p1 = __expf(sacc[nb][2 * r + 1] - nm);
                sacc[nb][2 * r] = p0; sacc[nb][2 * r + 1] = p1;
                rs += p0 + p1;
            }
            rs += __shfl_xor_sync(0xffffffffu, rs, 1);
            rs += __shfl_xor_sync(0xffffffffu, rs, 2);
            m[r] = nm;
            l[r] = l[r] * corr + rs;
#pragma unroll
            for (int nb = 0; nb < 16; nb++) {
                oacc[nb][2 * r]     *= corr;
                oacc[nb][2 * r + 1] *= corr;
            }
        }

#pragma unroll
        for (int kb = 0; kb < 4; kb++) {
            uint32_t a[4];
            a[0] = pack_h2(sacc[2 * kb][0],     sacc[2 * kb][1]);
            a[1] = pack_h2(sacc[2 * kb][2],     sacc[2 * kb][3]);
            a[2] = pack_h2(sacc[2 * kb + 1][0], sacc[2 * kb + 1][1]);
            a[3] = pack_h2(sacc[2 * kb + 1][2], sacc[2 * kb + 1][3]);
#pragma unroll
            for (int nb = 0; nb < 16; nb++) {
                uint2 bb = *reinterpret_cast<const uint2*>(
                    &Vst[kb * 1024 + nb * 64 + (lane << 1)]);
                MMA_F16(oacc[nb], a, (reinterpret_cast<uint32_t*>(&bb)));
            }
        }
    }

    const float inv0 = 1.f / l[0];
    const float inv1 = 1.f / l[1];
    const int t0 = b * SEQ + q0 + qrow + gid;
#pragma unroll
    for (int nb = 0; nb < 16; nb++) {
        int c = nb * 8 + 2 * tig;
        float2 v0 = {oacc[nb][0] * inv0, oacc[nb][1] * inv0};
        float2 v1 = {oacc[nb][2] * inv1, oacc[nb][3] * inv1};
        *reinterpret_cast<float2*>(out + (size_t)t0 * (NH * HDIM) + h * HDIM + c) = v0;
        *reinterpret_cast<float2*>(out + (size_t)(t0 + 8) * (NH * HDIM) + h * HDIM + c) = v1;
    }
}

// ---------------------------------------------------------------------------
extern "C" void kernel_launch(void* const* d_in, const int* in_sizes, int n_in,
                              void* d_out, int out_size) {
    const float* hidden = (const float*)d_in[0];
    const float* w_qkv  = (const float*)d_in[1];
    const float* cosT   = (const float*)d_in[2];
    const float* sinT   = (const float*)d_in[3];
    float* out = (float*)d_out;

    cudaFuncSetAttribute(gemm_f16_kernel, cudaFuncAttributeMaxDynamicSharedMemorySize, 98304);
    cudaFuncSetAttribute(attn_tc_kernel, cudaFuncAttributeMaxDynamicSharedMemorySize, ATTN_SMEM);

    pack_a_kernel<<<(T_TOK * DMODEL / 4) / 256, 256>>>(hidden);
    pack_w_kernel<<<(DMODEL / 2 * (QKVC / 4)) / 256, 256>>>(w_qkv);

    dim3 ggrid(QKVC / 128, T_TOK / 128);   // (48, 16)
    gemm_f16_kernel<<<ggrid, 128, 98304>>>();

    rope_packqkv_kernel<<<ROPE_BLOCKS + PACKV_BLOCKS, 256>>>(cosT, sinT);

    dim3 agrid(SEQ / 128, NBATCH * NH);    // (8, 64)
    attn_tc_kernel<<<agrid, 256, ATTN_SMEM>>>(out);
}

// round 15
// speedup vs baseline: 1.0084x; 1.0084x over previous
#include <cuda_runtime.h>
#include <cuda_fp16.h>
#include <cstdint>

// Problem constants (B=2, S=1024, H=32, KVH=8, HD=128, DM=4096)
#define T_TOK   2048
#define DMODEL  4096
#define QKVC    6144
#define NH      32
#define NKV     8
#define HDIM    128
#define SEQ     1024
#define NBATCH  2
#define QSCALE  0.08838834764831845f

__device__ uint32_t g_pa[(size_t)T_TOK * DMODEL / 2];      // packed fp16 A tiles (GEMM)
__device__ uint32_t g_pb[(size_t)QKVC * DMODEL / 2];       // packed fp16 W tiles (GEMM)
__device__ uint32_t g_pq[(size_t)T_TOK * NH * HDIM / 2];   // Q A-frag tiles (post-rope)
__device__ uint32_t g_pk[(size_t)T_TOK * NKV * HDIM / 2];  // K B-frag tiles (post-rope)
__device__ uint32_t g_pv[(size_t)T_TOK * NKV * HDIM / 2];  // V B-frag tiles (transposed)

__device__ __forceinline__ uint32_t pack_h2(float lo, float hi) {
    __half2 h = __floats2half2_rn(lo, hi);
    return *reinterpret_cast<uint32_t*>(&h);
}
__device__ __forceinline__ float2 unpack_h2(uint32_t u) {
    __half2 h = *reinterpret_cast<__half2*>(&u);
    return __half22float2(h);
}

#define MMA_F16(d, a, b)                                                      \
    asm volatile(                                                             \
        "mma.sync.aligned.m16n8k16.row.col.f32.f16.f16.f32 "                  \
        "{%0,%1,%2,%3},{%4,%5,%6,%7},{%8,%9},{%0,%1,%2,%3};"                  \
        : "+f"(d[0]), "+f"(d[1]), "+f"(d[2]), "+f"(d[3])                      \
        : "r"(a[0]), "r"(a[1]), "r"(a[2]), "r"(a[3]), "r"(b[0]), "r"(b[1]))

__device__ __forceinline__ void cp_async16(uint32_t smem_addr, const void* gptr) {
    asm volatile("cp.async.cg.shared.global [%0], [%1], 16;"
                 :: "r"(smem_addr), "l"(gptr) : "memory");
}
#define CP_COMMIT() asm volatile("cp.async.commit_group;" ::: "memory")
#define CP_WAIT1()  asm volatile("cp.async.wait_group 1;" ::: "memory")

// ---------------------------------------------------------------------------
// Kernel 0a/0b: pack A and W for the GEMM (verified layouts, unchanged).
// ---------------------------------------------------------------------------
__global__ __launch_bounds__(256) void pack_a_kernel(const float* __restrict__ A) {
    int i = blockIdx.x * 256 + threadIdx.x;
    int r  = i >> 10;
    int k0 = (i & 1023) << 2;
    float4 v = *reinterpret_cast<const float4*>(A + (size_t)r * DMODEL + k0);

    int mTile = r >> 7, rLoc = r & 127;
    int kTile = k0 >> 4, kLoc = k0 & 15;
    uint32_t* dst = g_pa + ((size_t)(mTile * (DMODEL / 16) + kTile)) * 1024;

    int rb = rLoc >> 4, r16 = rLoc & 15;
    int reg = ((kLoc >= 8) ? 2 : 0) + ((r16 >= 8) ? 1 : 0);
    int lane0 = (r16 & 7) * 4 + ((kLoc >> 1) & 3);
    int base = rb * 128;
    dst[base + lane0 * 4 + reg]       = pack_h2(v.x, v.y);
    dst[base + (lane0 + 1) * 4 + reg] = pack_h2(v.z, v.w);
}

__global__ __launch_bounds__(256) void pack_w_kernel(const float* __restrict__ W) {
    int i = blockIdx.x * 256 + threadIdx.x;
    int kp = i / 1536;
    int n0 = (i - kp * 1536) << 2;
    int k  = kp * 2;
    float4 vlo = *reinterpret_cast<const float4*>(W + (size_t)k * QKVC + n0);
    float4 vhi = *reinterpret_cast<const float4*>(W + (size_t)(k + 1) * QKVC + n0);

    int nTile = n0 >> 7, nLoc0 = n0 & 127;
    int kTile = k >> 4,  kLoc  = k & 15;
    uint32_t* dst = g_pb + ((size_t)(nTile * (DMODEL / 16) + kTile)) * 1024;

    int tig = (kLoc >> 1) & 3;
    int reg = (kLoc >= 8) ? 1 : 0;
    float lo[4] = {vlo.x, vlo.y, vlo.z, vlo.w};
    float hi[4] = {vhi.x, vhi.y, vhi.z, vhi.w};
#pragma unroll
    for (int j = 0; j < 4; j++) {
        int n = nLoc0 + j;
        int nblk = n >> 3, nn = n & 7;
        dst[nblk * 64 + (nn * 4 + tig) * 2 + reg] = pack_h2(lo[j], hi[j]);
    }
}

// ---------------------------------------------------------------------------
// Kernel 1: QKV GEMM (R13 mainloop) + FUSED rope/pack epilogue.
// CTA 128x128, 256 threads (8 warps 2x4), warp tile 64x32, BK=64, 3 stages.
// N-tile 0..31 = Q head; 32..39 = K head; 40..47 = V head. Epilogue stages the
// fp16 tile in smem then writes g_pq / g_pk / g_pv directly.
// ---------------------------------------------------------------------------
__global__ __launch_bounds__(256, 2) void gemm_f16_kernel(const float* __restrict__ cosT,
                                                          const float* __restrict__ sinT) {
    extern __shared__ __align__(16) uint32_t smem[];

    const int tid  = threadIdx.x;
    const int wid  = tid >> 5;
    const int lane = tid & 31;
    const int gid  = lane >> 2;
    const int tig  = lane & 3;
    const int wm   = wid >> 2;
    const int wn   = wid & 3;

    const uint32_t smem_base = (uint32_t)__cvta_generic_to_shared(smem);
    const uint32_t* pa = g_pa + (size_t)blockIdx.y * (DMODEL / 16) * 1024;
    const uint32_t* pb = g_pb + (size_t)blockIdx.x * (DMODEL / 16) * 1024;

    const int NCH = DMODEL / 64;

#define ISSUE(ch, s)                                                           \
    do {                                                                       \
        uint32_t sa = smem_base + (uint32_t)(s) * 32768;                       \
        const uint32_t* gA = pa + (size_t)(ch) * 4096 + tid * 4;               \
        const uint32_t* gB = pb + (size_t)(ch) * 4096 + tid * 4;               \
        cp_async16(sa + tid * 16,           gA);                               \
        cp_async16(sa + tid * 16 + 4096,    gA + 1024);                        \
        cp_async16(sa + tid * 16 + 8192,    gA + 2048);                        \
        cp_async16(sa + tid * 16 + 12288,   gA + 3072);                        \
        cp_async16(sa + 16384 + tid * 16,         gB);                         \
        cp_async16(sa + 16384 + tid * 16 + 4096,  gB + 1024);                  \
        cp_async16(sa + 16384 + tid * 16 + 8192,  gB + 2048);                  \
        cp_async16(sa + 16384 + tid * 16 + 12288, gB + 3072);                  \
    } while (0)

    float acc[4][4][4];
#pragma unroll
    for (int i = 0; i < 4; i++)
#pragma unroll
        for (int j = 0; j < 4; j++)
#pragma unroll
            for (int c = 0; c < 4; c++) acc[i][j][c] = 0.f;

    ISSUE(0, 0); CP_COMMIT();
    ISSUE(1, 1); CP_COMMIT();
    CP_WAIT1();
    __syncthreads();

    for (int ch = 0; ch < NCH; ch++) {
        if (ch + 2 < NCH) ISSUE(ch + 2, (ch + 2) % 3);
        CP_COMMIT();

        const uint32_t* St = smem + (size_t)(ch % 3) * 8192;

#pragma unroll
        for (int kt = 0; kt < 4; kt++) {
            const uint32_t* As = St + kt * 1024;
            const uint32_t* Bs = St + 4096 + kt * 1024;
            uint4 av[4];
            uint2 bv[4];
#pragma unroll
            for (int i = 0; i < 4; i++)
                av[i] = *reinterpret_cast<const uint4*>(
                    &As[((wm << 2) + i) * 128 + (lane << 2)]);
#pragma unroll
            for (int j = 0; j < 4; j++)
                bv[j] = *reinterpret_cast<const uint2*>(
                    &Bs[((wn << 2) + j) * 64 + (lane << 1)]);
#pragma unroll
            for (int i = 0; i < 4; i++)
#pragma unroll
                for (int j = 0; j < 4; j++)
                    MMA_F16(acc[i][j], (reinterpret_cast<uint32_t*>(&av[i])),
                            (reinterpret_cast<uint32_t*>(&bv[j])));
        }

        CP_WAIT1();
        __syncthreads();   // final iteration's barrier also frees smem for epilogue
    }

    // ---- Fused epilogue: stage fp16 tile [128 rows][64 half2 words] in smem ----
    uint32_t* Ep = smem;
#pragma unroll
    for (int i = 0; i < 4; i++) {
#pragma unroll
        for (int j = 0; j < 4; j++) {
            int r  = wm * 64 + i * 16 + gid;
            int cp = wn * 16 + j * 4 + tig;
            Ep[r * 64 + cp]       = pack_h2(acc[i][j][0], acc[i][j][1]);
            Ep[(r + 8) * 64 + cp] = pack_h2(acc[i][j][2], acc[i][j][3]);
        }
    }
    __syncthreads();

    const int mtile = blockIdx.y;
    const int ntile = blockIdx.x;
    const int b = mtile >> 3;

    if (ntile < NH) {
        // ---- Q head: rope + scale + A-frag pack ----
        const int head = ntile;
        const int qblk = mtile & 7;
        uint32_t* dstbase = g_pq + ((size_t)((b * 8 + qblk) * 32 + head)) * 8192;
#pragma unroll
        for (int it = 0; it < 16; it++) {
            int idx = tid + it * 256;
            int rr = idx >> 5, j = idx & 31;
            int t = mtile * 128 + rr;
            float2 x1 = unpack_h2(Ep[rr * 64 + j]);
            float2 x2 = unpack_h2(Ep[rr * 64 + 32 + j]);
            float2 c  = *reinterpret_cast<const float2*>(cosT + t * HDIM + 2 * j);
            float2 s  = *reinterpret_cast<const float2*>(sinT + t * HDIM + 2 * j);
            float lo0 = (x1.x * c.x - x2.x * s.x) * QSCALE;
            float lo1 = (x1.y * c.y - x2.y * s.y) * QSCALE;
            float hi0 = (x2.x * c.x + x1.x * s.x) * QSCALE;
            float hi1 = (x2.y * c.y + x1.y * s.y) * QSCALE;

            int tg = j & 3, ktile = j >> 3;
            int rb = rr >> 4, r16 = rr & 15;
            int reg = ((((2 * j) & 15) >= 8) ? 2 : 0) + ((r16 >= 8) ? 1 : 0);
            int lane0 = (r16 & 7) * 4 + tg;
            uint32_t* dst = dstbase + rb * 128;
            dst[ktile * 1024 + lane0 * 4 + reg]       = pack_h2(lo0, lo1);
            dst[(ktile + 4) * 1024 + lane0 * 4 + reg] = pack_h2(hi0, hi1);
        }
    } else if (ntile < NH + NKV) {
        // ---- K head: rope + B-frag pack ----
        const int hkv = ntile - NH;
#pragma unroll
        for (int it = 0; it < 16; it++) {
            int idx = tid + it * 256;
            int rr = idx >> 5, j = idx & 31;
            int t = mtile * 128 + rr;
            float2 x1 = unpack_h2(Ep[rr * 64 + j]);
            float2 x2 = unpack_h2(Ep[rr * 64 + 32 + j]);
            float2 c  = *reinterpret_cast<const float2*>(cosT + t * HDIM + 2 * j);
            float2 s  = *reinterpret_cast<const float2*>(sinT + t * HDIM + 2 * j);
            float lo0 = x1.x * c.x - x2.x * s.x;
            float lo1 = x1.y * c.y - x2.y * s.y;
            float hi0 = x2.x * c.x + x1.x * s.x;
            float hi1 = x2.y * c.y + x1.y * s.y;

            int tg = j & 3, ktile = j >> 3;
            int kvblk = (mtile & 7) * 2 + (rr >> 6);
            int n = rr & 63, nblk = n >> 3, nn = n & 7;
            int reg = (((2 * j) & 15) >= 8) ? 1 : 0;
            uint32_t* dst = g_pk + ((size_t)((b * 8 + hkv) * 16 + kvblk)) * 4096
                            + nblk * 64 + (nn * 4 + tg) * 2 + reg;
            dst[ktile * 512]       = pack_h2(lo0, lo1);
            dst[(ktile + 4) * 512] = pack_h2(hi0, hi1);
        }
    } else {
        // ---- V head: transpose-pack (pairs of adjacent token rows) ----
        const int hkv = ntile - NH - NKV;
#pragma unroll
        for (int it = 0; it < 8; it++) {
            int idx = tid + it * 256;
            int tp = idx >> 5, dq = idx & 31;
            int rr = tp * 2;
            uint2 vlo = *reinterpret_cast<const uint2*>(&Ep[rr * 64 + dq * 2]);
            uint2 vhi = *reinterpret_cast<const uint2*>(&Ep[(rr + 1) * 64 + dq * 2]);

            int kvblk = (mtile & 7) * 2 + (rr >> 6);
            int kc = rr & 15;
            int tg = (kc >> 1) & 3;
            int reg = (kc >= 8) ? 1 : 0;
            int ktv = (rr & 63) >> 4;
            uint32_t* dst = g_pv + ((size_t)((b * 8 + hkv) * 16 + kvblk)) * 4096 + ktv * 1024;

            uint32_t w[4];
            w[0] = __byte_perm(vlo.x, vhi.x, 0x5410);
            w[1] = __byte_perm(vlo.x, vhi.x, 0x7632);
            w[2] = __byte_perm(vlo.y, vhi.y, 0x5410);
            w[3] = __byte_perm(vlo.y, vhi.y, 0x7632);
#pragma unroll
            for (int jj = 0; jj < 4; jj++) {
                int d = dq * 4 + jj;
                int nblk = d >> 3, nn = d & 7;
                dst[nblk * 64 + (nn * 4 + tg) * 2 + reg] = w[jj];
            }
        }
    }
}

// ---------------------------------------------------------------------------
// Kernel 3: fp16 flash attention (unchanged from R13 best).
// ---------------------------------------------------------------------------
#define ATTN_SMEM (3 * 8192 * 4)   // 98304

__global__ __launch_bounds__(256) void attn_tc_kernel(float* __restrict__ out) {
    extern __shared__ __align__(16) uint32_t sm[];
    const uint32_t smem_base = (uint32_t)__cvta_generic_to_shared(sm);

    const int tid  = threadIdx.x;
    const int wid  = tid >> 5;
    const int lane = tid & 31;
    const int gid  = lane >> 2;
    const int tig  = lane & 3;
    const int qrow = wid * 16;

    const int b   = blockIdx.y >> 5;
    const int h   = blockIdx.y & 31;
    const int kvh = h >> 2;
    const int q0  = blockIdx.x * 128;

    const uint32_t* qbase = g_pq + ((size_t)((b * 8 + blockIdx.x) * 32 + h)) * 8192;
    uint4 qa[8];
#pragma unroll
    for (int ks = 0; ks < 8; ks++)
        qa[ks] = *reinterpret_cast<const uint4*>(qbase + ks * 1024 + wid * 128 + lane * 4);

    const uint32_t* kbase = g_pk + ((size_t)((b * 8 + kvh) * 16)) * 4096;
    const uint32_t* vbase = g_pv + ((size_t)((b * 8 + kvh) * 16)) * 4096;

#define AISSUE(kt, s)                                                          \
    do {                                                                       \
        uint32_t sa = smem_base + (uint32_t)(s) * 32768;                       \
        const uint32_t* gK = kbase + (size_t)(kt) * 4096;                      \
        const uint32_t* gV = vbase + (size_t)(kt) * 4096;                      \
        _Pragma("unroll")                                                      \
        for (int i = 0; i < 4; i++) {                                          \
            int c = tid + i * 256;                                             \
            cp_async16(sa + c * 16,         gK + c * 4);                       \
            cp_async16(sa + 16384 + c * 16, gV + c * 4);                       \
        }                                                                      \
    } while (0)

    float m[2] = {-1e30f, -1e30f}, l[2] = {0.f, 0.f};
    float oacc[16][4];
#pragma unroll
    for (int nb = 0; nb < 16; nb++)
#pragma unroll
        for (int c = 0; c < 4; c++) oacc[nb][c] = 0.f;

    const int ktiles = 2 * (blockIdx.x + 1);
    AISSUE(0, 0); CP_COMMIT();
    AISSUE(1, 1); CP_COMMIT();

    for (int kt = 0; kt < ktiles; kt++) {
        const int kv0 = kt * 64;
        CP_WAIT1();
        __syncthreads();
        if (kt + 2 < ktiles) AISSUE(kt + 2, (kt + 2) % 3);
        CP_COMMIT();

        const uint32_t* Kst = sm + (size_t)(kt % 3) * 8192;
        const uint32_t* Vst = Kst + 4096;

        float sacc[8][4];
#pragma unroll
        for (int nb = 0; nb < 8; nb++)
#pragma unroll
            for (int c = 0; c < 4; c++) sacc[nb][c] = 0.f;

#pragma unroll
        for (int ks = 0; ks < 8; ks++) {
#pragma unroll
            for (int nb = 0; nb < 8; nb++) {
                uint2 bb = *reinterpret_cast<const uint2*>(
                    &Kst[ks * 512 + nb * 64 + (lane << 1)]);
                MMA_F16(sacc[nb], (reinterpret_cast<uint32_t*>(&qa[ks])),
                        (reinterpret_cast<uint32_t*>(&bb)));
            }
        }

        const int row0 = q0 + qrow + gid;
        const int row1 = row0 + 8;
        if (kv0 + 63 > row0) {
#pragma unroll
            for (int nb = 0; nb < 8; nb++) {
                int c0 = kv0 + nb * 8 + 2 * tig;
                if (c0 > row0)     sacc[nb][0] = -1e30f;
                if (c0 + 1 > row0) sacc[nb][1] = -1e30f;
                if (c0 > row1)     sacc[nb][2] = -1e30f;
                if (c0 + 1 > row1) sacc[nb][3] = -1e30f;
            }
        }

#pragma unroll
        for (int r = 0; r < 2; r++) {
            float rmax = -1e30f;
#pragma unroll
            for (int nb = 0; nb < 8; nb++)
                rmax = fmaxf(rmax, fmaxf(sacc[nb][2 * r], sacc[nb][2 * r + 1]));
            rmax = fmaxf(rmax, __shfl_xor_sync(0xffffffffu, rmax, 1));
            rmax = fmaxf(rmax, __shfl_xor_sync(0xffffffffu, rmax, 2));
            float nm = fmaxf(m[r], rmax);
            float corr = __expf(m[r] - nm);
            float rs = 0.f;
#pragma unroll
            for (int nb = 0; nb < 8; nb++) {
                float p0 = __expf(sacc[nb][2 * r]     - nm);
                float p1 = __expf(sacc[nb][2 * r + 1] - nm);
                sacc[nb][2 * r] = p0; sacc[nb][2 * r + 1] = p1;
                rs += p0 + p1;
            }
            rs += __shfl_xor_sync(0xffffffffu, rs, 1);
            rs += __shfl_xor_sync(0xffffffffu, rs, 2);
            m[r] = nm;
            l[r] = l[r] * corr + rs;
#pragma unroll
            for (int nb = 0; nb < 16; nb++) {
                oacc[nb][2 * r]     *= corr;
                oacc[nb][2 * r + 1] *= corr;
            }
        }

#pragma unroll
        for (int kb = 0; kb < 4; kb++) {
            uint32_t a[4];
            a[0] = pack_h2(sacc[2 * kb][0],     sacc[2 * kb][1]);
            a[1] = pack_h2(sacc[2 * kb][2],     sacc[2 * kb][3]);
            a[2] = pack_h2(sacc[2 * kb + 1][0], sacc[2 * kb + 1][1]);
            a[3] = pack_h2(sacc[2 * kb + 1][2], sacc[2 * kb + 1][3]);
#pragma unroll
            for (int nb = 0; nb < 16; nb++) {
                uint2 bb = *reinterpret_cast<const uint2*>(
                    &Vst[kb * 1024 + nb * 64 + (lane << 1)]);
                MMA_F16(oacc[nb], a, (reinterpret_cast<uint32_t*>(&bb)));
            }
        }
    }

    const float inv0 = 1.f / l[0];
    const float inv1 = 1.f / l[1];
    const int t0 = b * SEQ + q0 + qrow + gid;
#pragma unroll
    for (int nb = 0; nb < 16; nb++) {
        int c = nb * 8 + 2 * tig;
        float2 v0 = {oacc[nb][0] * inv0, oacc[nb][1] * inv0};
        float2 v1 = {oacc[nb][2] * inv1, oacc[nb][3] * inv1};
        *reinterpret_cast<float2*>(out + (size_t)t0 * (NH * HDIM) + h * HDIM + c) = v0;
        *reinterpret_cast<float2*>(out + (size_t)(t0 + 8) * (NH * HDIM) + h * HDIM + c) = v1;
    }
}

// ---------------------------------------------------------------------------
extern "C" void kernel_launch(void* const* d_in, const int* in_sizes, int n_in,
                              void* d_out, int out_size) {
    const float* hidden = (const float*)d_in[0];
    const float* w_qkv  = (const float*)d_in[1];
    const float* cosT   = (const float*)d_in[2];
    const float* sinT   = (const float*)d_in[3];
    float* out = (float*)d_out;

    cudaFuncSetAttribute(gemm_f16_kernel, cudaFuncAttributeMaxDynamicSharedMemorySize, 98304);
    cudaFuncSetAttribute(attn_tc_kernel, cudaFuncAttributeMaxDynamicSharedMemorySize, ATTN_SMEM);

    pack_a_kernel<<<(T_TOK * DMODEL / 4) / 256, 256>>>(hidden);
    pack_w_kernel<<<(DMODEL / 2 * (QKVC / 4)) / 256, 256>>>(w_qkv);

    dim3 ggrid(QKVC / 128, T_TOK / 128);   // (48, 16)
    gemm_f16_kernel<<<ggrid, 256, 98304>>>(cosT, sinT);

    dim3 agrid(SEQ / 128, NBATCH * NH);    // (8, 64)
    attn_tc_kernel<<<agrid, 256, ATTN_SMEM>>>(out);
}

// round 16
// speedup vs baseline: 1.1634x; 1.1537x over previous
#include <cuda_runtime.h>
#include <cuda_fp16.h>
#include <cstdint>

// Problem constants (B=2, S=1024, H=32, KVH=8, HD=128, DM=4096)
#define T_TOK   2048
#define DMODEL  4096
#define QKVC    6144
#define NH      32
#define NKV     8
#define HDIM    128
#define SEQ     1024
#define NBATCH  2
#define QSCALE  0.08838834764831845f

__device__ uint32_t g_qkvh[(size_t)T_TOK * QKVC / 2];      // GEMM output, fp16 half2
__device__ uint32_t g_pa[(size_t)T_TOK * DMODEL / 2];      // packed fp16 A tiles (GEMM)
__device__ uint32_t g_pb[(size_t)QKVC * DMODEL / 2];       // packed fp16 W tiles (GEMM)
__device__ uint32_t g_pq[(size_t)T_TOK * NH * HDIM / 2];   // Q A-frag tiles (post-rope)
__device__ uint32_t g_pk[(size_t)T_TOK * NKV * HDIM / 2];  // K B-frag tiles (post-rope)
__device__ uint32_t g_pv[(size_t)T_TOK * NKV * HDIM / 2];  // V B-frag tiles (transposed)

__device__ __forceinline__ uint32_t pack_h2(float lo, float hi) {
    __half2 h = __floats2half2_rn(lo, hi);
    return *reinterpret_cast<uint32_t*>(&h);
}
__device__ __forceinline__ float2 unpack_h2(uint32_t u) {
    __half2 h = *reinterpret_cast<__half2*>(&u);
    return __half22float2(h);
}

#define MMA_F16(d, a, b)                                                      \
    asm volatile(                                                             \
        "mma.sync.aligned.m16n8k16.row.col.f32.f16.f16.f32 "                  \
        "{%0,%1,%2,%3},{%4,%5,%6,%7},{%8,%9},{%0,%1,%2,%3};"                  \
        : "+f"(d[0]), "+f"(d[1]), "+f"(d[2]), "+f"(d[3])                      \
        : "r"(a[0]), "r"(a[1]), "r"(a[2]), "r"(a[3]), "r"(b[0]), "r"(b[1]))

__device__ __forceinline__ void cp_async16(uint32_t smem_addr, const void* gptr) {
    asm volatile("cp.async.cg.shared.global [%0], [%1], 16;"
                 :: "r"(smem_addr), "l"(gptr) : "memory");
}
#define CP_COMMIT() asm volatile("cp.async.commit_group;" ::: "memory")
#define CP_WAIT1()  asm volatile("cp.async.wait_group 1;" ::: "memory")

// ---------------------------------------------------------------------------
// Kernel 0a: pack A via smem staging (coalesced loads AND stores).
// CTA = (kblk: 64 k-cols, mTile: 128 rows). smem tile = 4 ktiles, stride 1032.
// ---------------------------------------------------------------------------
__global__ __launch_bounds__(256) void pack_a_kernel(const float* __restrict__ A) {
    __shared__ uint32_t ps[4 * 1032];   // 16.5 KB
    const int tid = threadIdx.x;
    const int kblk = blockIdx.x;        // 0..63
    const int mTile = blockIdx.y;       // 0..15
    const float* Ab = A + (size_t)(mTile * 128) * DMODEL + kblk * 64;

#pragma unroll
    for (int it = 0; it < 8; it++) {
        int idx = tid + it * 256;       // 0..2047
        int r  = idx >> 4;              // 0..127
        int c4 = (idx & 15) << 2;       // 0..60
        float4 v = *reinterpret_cast<const float4*>(Ab + (size_t)r * DMODEL + c4);
        int kt = c4 >> 4, kLoc = c4 & 15;
        int rb = r >> 4, r16 = r & 15;
        int reg = ((kLoc >= 8) ? 2 : 0) + ((r16 >= 8) ? 1 : 0);
        int lane0 = (r16 & 7) * 4 + ((kLoc >> 1) & 3);
        int base = kt * 1032 + rb * 128;
        ps[base + lane0 * 4 + reg]       = pack_h2(v.x, v.y);
        ps[base + (lane0 + 1) * 4 + reg] = pack_h2(v.z, v.w);
    }
    __syncthreads();

    uint32_t* dst = g_pa + ((size_t)(mTile * (DMODEL / 16) + kblk * 4)) * 1024;
#pragma unroll
    for (int kt = 0; kt < 4; kt++) {
        uint4 v = *reinterpret_cast<const uint4*>(&ps[kt * 1032 + tid * 4]);
        *reinterpret_cast<uint4*>(dst + kt * 1024 + tid * 4) = v;
    }
}

// ---------------------------------------------------------------------------
// Kernel 0b: pack W via smem staging.
// CTA = (nTile: 128 cols, kblk: 64 k-rows). smem: 4 ktiles x 16 nblk x 66.
// ---------------------------------------------------------------------------
__global__ __launch_bounds__(256) void pack_w_kernel(const float* __restrict__ W) {
    __shared__ uint32_t ps[4 * 1056];   // 16.9 KB (nblk stride 66)
    const int tid = threadIdx.x;
    const int nTile = blockIdx.x;       // 0..47
    const int kblk  = blockIdx.y;       // 0..63
    const float* Wb = W + (size_t)(kblk * 64) * QKVC + nTile * 128;

#pragma unroll
    for (int it = 0; it < 4; it++) {
        int idx = tid + it * 256;       // 0..1023
        int kp   = idx >> 5;            // 0..31 (k pair)
        int lane = idx & 31;
        int k = kp * 2;
        const float* row = Wb + (size_t)k * QKVC + lane * 4;
        float4 vlo = *reinterpret_cast<const float4*>(row);
        float4 vhi = *reinterpret_cast<const float4*>(row + QKVC);

        int kt  = kp >> 3;
        int tg  = kp & 3;
        int reg = ((kp & 7) >= 4) ? 1 : 0;
        float lo[4] = {vlo.x, vlo.y, vlo.z, vlo.w};
        float hi[4] = {vhi.x, vhi.y, vhi.z, vhi.w};
#pragma unroll
        for (int j = 0; j < 4; j++) {
            int n = lane * 4 + j;
            int nblk = n >> 3, nn = n & 7;
            ps[kt * 1056 + nblk * 66 + (nn * 4 + tg) * 2 + reg] = pack_h2(lo[j], hi[j]);
        }
    }
    __syncthreads();

    // Copy out: 64 chunks (4 kt x 16 nblk) of 64 words; warp per chunk-slice.
    uint32_t* dst = g_pb + ((size_t)(nTile * (DMODEL / 16) + kblk * 4)) * 1024;
    const int wid  = tid >> 5;
    const int lane = tid & 31;
#pragma unroll
    for (int wi = 0; wi < 8; wi++) {
        int c = wid * 8 + wi;           // 0..63
        int kt = c >> 4, nblk = c & 15;
        uint2 v = *reinterpret_cast<const uint2*>(&ps[kt * 1056 + nblk * 66 + lane * 2]);
        *reinterpret_cast<uint2*>(dst + kt * 1024 + nblk * 64 + lane * 2) = v;
    }
}

// ---------------------------------------------------------------------------
// Kernel 1: QKV GEMM (R13-proven: fp16 m16n8k16, BK=64, 3 stages, 96KB,
// 256 threads / 8 warps 2x4, warp tile 64x32; fp16 epilogue).
// ---------------------------------------------------------------------------
__global__ __launch_bounds__(256, 2) void gemm_f16_kernel() {
    extern __shared__ __align__(16) uint32_t smem[];

    const int tid  = threadIdx.x;
    const int wid  = tid >> 5;
    const int lane = tid & 31;
    const int gid  = lane >> 2;
    const int tig  = lane & 3;
    const int wm   = wid >> 2;
    const int wn   = wid & 3;

    const uint32_t smem_base = (uint32_t)__cvta_generic_to_shared(smem);
    const uint32_t* pa = g_pa + (size_t)blockIdx.y * (DMODEL / 16) * 1024;
    const uint32_t* pb = g_pb + (size_t)blockIdx.x * (DMODEL / 16) * 1024;

    const int NCH = DMODEL / 64;

#define ISSUE(ch, s)                                                           \
    do {                                                                       \
        uint32_t sa = smem_base + (uint32_t)(s) * 32768;                       \
        const uint32_t* gA = pa + (size_t)(ch) * 4096 + tid * 4;               \
        const uint32_t* gB = pb + (size_t)(ch) * 4096 + tid * 4;               \
        cp_async16(sa + tid * 16,           gA);                               \
        cp_async16(sa + tid * 16 + 4096,    gA + 1024);                        \
        cp_async16(sa + tid * 16 + 8192,    gA + 2048);                        \
        cp_async16(sa + tid * 16 + 12288,   gA + 3072);                        \
        cp_async16(sa + 16384 + tid * 16,         gB);                         \
        cp_async16(sa + 16384 + tid * 16 + 4096,  gB + 1024);                  \
        cp_async16(sa + 16384 + tid * 16 + 8192,  gB + 2048);                  \
        cp_async16(sa + 16384 + tid * 16 + 12288, gB + 3072);                  \
    } while (0)

    float acc[4][4][4];
#pragma unroll
    for (int i = 0; i < 4; i++)
#pragma unroll
        for (int j = 0; j < 4; j++)
#pragma unroll
            for (int c = 0; c < 4; c++) acc[i][j][c] = 0.f;

    ISSUE(0, 0); CP_COMMIT();
    ISSUE(1, 1); CP_COMMIT();
    CP_WAIT1();
    __syncthreads();

    for (int ch = 0; ch < NCH; ch++) {
        if (ch + 2 < NCH) ISSUE(ch + 2, (ch + 2) % 3);
        CP_COMMIT();

        const uint32_t* St = smem + (size_t)(ch % 3) * 8192;

#pragma unroll
        for (int kt = 0; kt < 4; kt++) {
            const uint32_t* As = St + kt * 1024;
            const uint32_t* Bs = St + 4096 + kt * 1024;
            uint4 av[4];
            uint2 bv[4];
#pragma unroll
            for (int i = 0; i < 4; i++)
                av[i] = *reinterpret_cast<const uint4*>(
                    &As[((wm << 2) + i) * 128 + (lane << 2)]);
#pragma unroll
            for (int j = 0; j < 4; j++)
                bv[j] = *reinterpret_cast<const uint2*>(
                    &Bs[((wn << 2) + j) * 64 + (lane << 1)]);
#pragma unroll
            for (int i = 0; i < 4; i++)
#pragma unroll
                for (int j = 0; j < 4; j++)
                    MMA_F16(acc[i][j], (reinterpret_cast<uint32_t*>(&av[i])),
                            (reinterpret_cast<uint32_t*>(&bv[j])));
        }

        CP_WAIT1();
        __syncthreads();
    }

    uint32_t* C = g_qkvh + (size_t)blockIdx.y * 128 * (QKVC / 2) + blockIdx.x * 64;
#pragma unroll
    for (int i = 0; i < 4; i++) {
#pragma unroll
        for (int j = 0; j < 4; j++) {
            int r = wm * 64 + i * 16 + gid;
            int cp = wn * 16 + j * 4 + tig;
            C[(size_t)(r)     * (QKVC / 2) + cp] = pack_h2(acc[i][j][0], acc[i][j][1]);
            C[(size_t)(r + 8) * (QKVC / 2) + cp] = pack_h2(acc[i][j][2], acc[i][j][3]);
        }
    }
}

// ---------------------------------------------------------------------------
// Kernel 2 (fused): RoPE+pack Q/K, then pack V (block-range split). (R13)
// ---------------------------------------------------------------------------
#define ROPE_BLOCKS 10240
#define PACKV_BLOCKS 1024

__global__ __launch_bounds__(256) void rope_packqkv_kernel(const float* __restrict__ cosT,
                                                           const float* __restrict__ sinT) {
    if (blockIdx.x < ROPE_BLOCKS) {
        int idx = blockIdx.x * 256 + threadIdx.x;
        int j    = idx & 31;
        int head = (idx >> 5) % 40;
        int t    = idx / (32 * 40);
        int d0   = 2 * j;

        const uint32_t* p = g_qkvh + (size_t)t * (QKVC / 2) + head * 64;
        float2 x1 = unpack_h2(p[j]);
        float2 x2 = unpack_h2(p[32 + j]);
        float2 c  = *reinterpret_cast<const float2*>(cosT + t * HDIM + d0);
        float2 s  = *reinterpret_cast<const float2*>(sinT + t * HDIM + d0);

        float lo0 = x1.x * c.x - x2.x * s.x;
        float lo1 = x1.y * c.y - x2.y * s.y;
        float hi0 = x2.x * c.x + x1.x * s.x;
        float hi1 = x2.y * c.y + x1.y * s.y;

        int b = t >> 10;
        int tig = j & 3;
        int ktile = j >> 3;
        if (head < NH) {
            lo0 *= QSCALE; lo1 *= QSCALE; hi0 *= QSCALE; hi1 *= QSCALE;
            int qblk = (t & 1023) >> 7;
            int rLoc = t & 127, rb = rLoc >> 4, r16 = rLoc & 15;
            int reg = (((d0 & 15) >= 8) ? 2 : 0) + ((r16 >= 8) ? 1 : 0);
            int lane0 = (r16 & 7) * 4 + tig;
            uint32_t* dst = g_pq + ((size_t)((b * 8 + qblk) * 32 + head)) * 8192 + rb * 128;
            dst[ktile * 1024 + lane0 * 4 + reg]       = pack_h2(lo0, lo1);
            dst[(ktile + 4) * 1024 + lane0 * 4 + reg] = pack_h2(hi0, hi1);
        } else {
            int hkv = head - NH;
            int kvblk = (t & 1023) >> 6;
            int n = t & 63, nblk = n >> 3, nn = n & 7;
            int reg = ((d0 & 15) >= 8) ? 1 : 0;
            uint32_t* dst = g_pk + ((size_t)((b * 8 + hkv) * 16 + kvblk)) * 4096
                            + nblk * 64 + (nn * 4 + tig) * 2 + reg;
            dst[ktile * 512]       = pack_h2(lo0, lo1);
            dst[(ktile + 4) * 512] = pack_h2(hi0, hi1);
        }
    } else {
        int idx = (blockIdx.x - ROPE_BLOCKS) * 256 + threadIdx.x;
        int dq  = idx & 31;
        int hkv = (idx >> 5) & 7;
        int tp  = idx >> 8;
        int t   = tp * 2;
        int d0  = dq * 4;

        const uint32_t* Vg = g_qkvh + (size_t)t * (QKVC / 2) + (NH + NKV + hkv) * 64 + (d0 >> 1);
        uint2 vlo = *reinterpret_cast<const uint2*>(Vg);
        uint2 vhi = *reinterpret_cast<const uint2*>(Vg + (QKVC / 2));

        int b = t >> 10;
        int kvblk = (t & 1023) >> 6;
        int kc = t & 15;
        int tig = (kc >> 1) & 3;
        int reg = (kc >= 8) ? 1 : 0;
        int ktv = (t & 63) >> 4;
        uint32_t* dst = g_pv + ((size_t)((b * 8 + hkv) * 16 + kvblk)) * 4096 + ktv * 1024;

        uint32_t w[4];
        w[0] = __byte_perm(vlo.x, vhi.x, 0x5410);
        w[1] = __byte_perm(vlo.x, vhi.x, 0x7632);
        w[2] = __byte_perm(vlo.y, vhi.y, 0x5410);
        w[3] = __byte_perm(vlo.y, vhi.y, 0x7632);
#pragma unroll
        for (int jj = 0; jj < 4; jj++) {
            int d = d0 + jj;
            int nblk = d >> 3, nn = d & 7;
            dst[nblk * 64 + (nn * 4 + tig) * 2 + reg] = w[jj];
        }
    }
}

// ---------------------------------------------------------------------------
// Kernel 3: fp16 flash attention (unchanged from R12/R13 best).
// ---------------------------------------------------------------------------
#define ATTN_SMEM (3 * 8192 * 4)   // 98304

__global__ __launch_bounds__(256) void attn_tc_kernel(float* __restrict__ out) {
    extern __shared__ __align__(16) uint32_t sm[];
    const uint32_t smem_base = (uint32_t)__cvta_generic_to_shared(sm);

    const int tid  = threadIdx.x;
    const int wid  = tid >> 5;
    const int lane = tid & 31;
    const int gid  = lane >> 2;
    const int tig  = lane & 3;
    const int qrow = wid * 16;

    const int b   = blockIdx.y >> 5;
    const int h   = blockIdx.y & 31;
    const int kvh = h >> 2;
    const int q0  = blockIdx.x * 128;

    const uint32_t* qbase = g_pq + ((size_t)((b * 8 + blockIdx.x) * 32 + h)) * 8192;
    uint4 qa[8];
#pragma unroll
    for (int ks = 0; ks < 8; ks++)
        qa[ks] = *reinterpret_cast<const uint4*>(qbase + ks * 1024 + wid * 128 + lane * 4);

    const uint32_t* kbase = g_pk + ((size_t)((b * 8 + kvh) * 16)) * 4096;
    const uint32_t* vbase = g_pv + ((size_t)((b * 8 + kvh) * 16)) * 4096;

#define AISSUE(kt, s)                                                          \
    do {                                                                       \
        uint32_t sa = smem_base + (uint32_t)(s) * 32768;                       \
        const uint32_t* gK = kbase + (size_t)(kt) * 4096;                      \
        const uint32_t* gV = vbase + (size_t)(kt) * 4096;                      \
        _Pragma("unroll")                                                      \
        for (int i = 0; i < 4; i++) {                                          \
            int c = tid + i * 256;                                             \
            cp_async16(sa + c * 16,         gK + c * 4);                       \
            cp_async16(sa + 16384 + c * 16, gV + c * 4);                       \
        }                                                                      \
    } while (0)

    float m[2] = {-1e30f, -1e30f}, l[2] = {0.f, 0.f};
    float oacc[16][4];
#pragma unroll
    for (int nb = 0; nb < 16; nb++)
#pragma unroll
        for (int c = 0; c < 4; c++) oacc[nb][c] = 0.f;

    const int ktiles = 2 * (blockIdx.x + 1);
    AISSUE(0, 0); CP_COMMIT();
    AISSUE(1, 1); CP_COMMIT();

    for (int kt = 0; kt < ktiles; kt++) {
        const int kv0 = kt * 64;
        CP_WAIT1();
        __syncthreads();
        if (kt + 2 < ktiles) AISSUE(kt + 2, (kt + 2) % 3);
        CP_COMMIT();

        const uint32_t* Kst = sm + (size_t)(kt % 3) * 8192;
        const uint32_t* Vst = Kst + 4096;

        float sacc[8][4];
#pragma unroll
        for (int nb = 0; nb < 8; nb++)
#pragma unroll
            for (int c = 0; c < 4; c++) sacc[nb][c] = 0.f;

#pragma unroll
        for (int ks = 0; ks < 8; ks++) {
#pragma unroll
            for (int nb = 0; nb < 8; nb++) {
                uint2 bb = *reinterpret_cast<const uint2*>(
                    &Kst[ks * 512 + nb * 64 + (lane << 1)]);
                MMA_F16(sacc[nb], (reinterpret_cast<uint32_t*>(&qa[ks])),
                        (reinterpret_cast<uint32_t*>(&bb)));
            }
        }

        const int row0 = q0 + qrow + gid;
        const int row1 = row0 + 8;
        if (kv0 + 63 > row0) {
#pragma unroll
            for (int nb = 0; nb < 8; nb++) {
                int c0 = kv0 + nb * 8 + 2 * tig;
                if (c0 > row0)     sacc[nb][0] = -1e30f;
                if (c0 + 1 > row0) sacc[nb][1] = -1e30f;
                if (c0 > row1)     sacc[nb][2] = -1e30f;
                if (c0 + 1 > row1) sacc[nb][3] = -1e30f;
            }
        }

#pragma unroll
        for (int r = 0; r < 2; r++) {
            float rmax = -1e30f;
#pragma unroll
            for (int nb = 0; nb < 8; nb++)
                rmax = fmaxf(rmax, fmaxf(sacc[nb][2 * r], sacc[nb][2 * r + 1]));
            rmax = fmaxf(rmax, __shfl_xor_sync(0xffffffffu, rmax, 1));
            rmax = fmaxf(rmax, __shfl_xor_sync(0xffffffffu, rmax, 2));
            float nm = fmaxf(m[r], rmax);
            float corr = __expf(m[r] - nm);
            float rs = 0.f;
#pragma unroll
            for (int nb = 0; nb < 8; nb++) {
                float p0 = __expf(sacc[nb][2 * r]     - nm);
                float p1 = __expf(sacc[nb][2 * r + 1] - nm);
                sacc[nb][2 * r] = p0; sacc[nb][2 * r + 1] = p1;
                rs += p0 + p1;
            }
            rs += __shfl_xor_sync(0xffffffffu, rs, 1);
            rs += __shfl_xor_sync(0xffffffffu, rs, 2);
            m[r] = nm;
            l[r] = l[r] * corr + rs;
#pragma unroll
            for (int nb = 0; nb < 16; nb++) {
                oacc[nb][2 * r]     *= corr;
                oacc[nb][2 * r + 1] *= corr;
            }
        }

#pragma unroll
        for (int kb = 0; kb < 4; kb++) {
            uint32_t a[4];
            a[0] = pack_h2(sacc[2 * kb][0],     sacc[2 * kb][1]);
            a[1] = pack_h2(sacc[2 * kb][2],     sacc[2 * kb][3]);
            a[2] = pack_h2(sacc[2 * kb + 1][0], sacc[2 * kb + 1][1]);
            a[3] = pack_h2(sacc[2 * kb + 1][2], sacc[2 * kb + 1][3]);
#pragma unroll
            for (int nb = 0; nb < 16; nb++) {
                uint2 bb = *reinterpret_cast<const uint2*>(
                    &Vst[kb * 1024 + nb * 64 + (lane << 1)]);
                MMA_F16(oacc[nb], a, (reinterpret_cast<uint32_t*>(&bb)));
            }
        }
    }

    const float inv0 = 1.f / l[0];
    const float inv1 = 1.f / l[1];
    const int t0 = b * SEQ + q0 + qrow + gid;
#pragma unroll
    for (int nb = 0; nb < 16; nb++) {
        int c = nb * 8 + 2 * tig;
        float2 v0 = {oacc[nb][0] * inv0, oacc[nb][1] * inv0};
        float2 v1 = {oacc[nb][2] * inv1, oacc[nb][3] * inv1};
        *reinterpret_cast<float2*>(out + (size_t)t0 * (NH * HDIM) + h * HDIM + c) = v0;
        *reinterpret_cast<float2*>(out + (size_t)(t0 + 8) * (NH * HDIM) + h * HDIM + c) = v1;
    }
}

// ---------------------------------------------------------------------------
extern "C" void kernel_launch(void* const* d_in, const int* in_sizes, int n_in,
                              void* d_out, int out_size) {
    const float* hidden = (const float*)d_in[0];
    const float* w_qkv  = (const float*)d_in[1];
    const float* cosT   = (const float*)d_in[2];
    const float* sinT   = (const float*)d_in[3];
    float* out = (float*)d_out;

    cudaFuncSetAttribute(gemm_f16_kernel, cudaFuncAttributeMaxDynamicSharedMemorySize, 98304);
    cudaFuncSetAttribute(attn_tc_kernel, cudaFuncAttributeMaxDynamicSharedMemorySize, ATTN_SMEM);

    pack_a_kernel<<<dim3(DMODEL / 64, T_TOK / 128), 256>>>(hidden);   // (64,16)
    pack_w_kernel<<<dim3(QKVC / 128, DMODEL / 64), 256>>>(w_qkv);     // (48,64)

    dim3 ggrid(QKVC / 128, T_TOK / 128);   // (48, 16)
    gemm_f16_kernel<<<ggrid, 256, 98304>>>();

    rope_packqkv_kernel<<<ROPE_BLOCKS + PACKV_BLOCKS, 256>>>(cosT, sinT);

    dim3 agrid(SEQ / 128, NBATCH * NH);    // (8, 64)
    attn_tc_kernel<<<agrid, 256, ATTN_SMEM>>>(out);
}

// round 17
// speedup vs baseline: 1.1781x; 1.0126x over previous
#include <cuda_runtime.h>
#include <cuda_fp16.h>
#include <cstdint>

// Problem constants (B=2, S=1024, H=32, KVH=8, HD=128, DM=4096)
#define T_TOK   2048
#define DMODEL  4096
#define QKVC    6144
#define NH      32
#define NKV     8
#define HDIM    128
#define SEQ     1024
#define NBATCH  2
#define QSCALE  0.08838834764831845f

__device__ uint32_t g_qkvh[(size_t)T_TOK * QKVC / 2];      // GEMM output, fp16 half2
__device__ uint32_t g_pa[(size_t)T_TOK * DMODEL / 2];      // packed fp16 A tiles (GEMM)
__device__ uint32_t g_pb[(size_t)QKVC * DMODEL / 2];       // packed fp16 W tiles (GEMM)
__device__ uint32_t g_pq[(size_t)T_TOK * NH * HDIM / 2];   // Q A-frag tiles (post-rope)
__device__ uint32_t g_pk[(size_t)T_TOK * NKV * HDIM / 2];  // K B-frag tiles (post-rope)
__device__ uint32_t g_pv[(size_t)T_TOK * NKV * HDIM / 2];  // V B-frag tiles (transposed)

__device__ __forceinline__ uint32_t pack_h2(float lo, float hi) {
    __half2 h = __floats2half2_rn(lo, hi);
    return *reinterpret_cast<uint32_t*>(&h);
}
__device__ __forceinline__ float2 unpack_h2(uint32_t u) {
    __half2 h = *reinterpret_cast<__half2*>(&u);
    return __half22float2(h);
}

#define MMA_F16(d, a, b)                                                      \
    asm volatile(                                                             \
        "mma.sync.aligned.m16n8k16.row.col.f32.f16.f16.f32 "                  \
        "{%0,%1,%2,%3},{%4,%5,%6,%7},{%8,%9},{%0,%1,%2,%3};"                  \
        : "+f"(d[0]), "+f"(d[1]), "+f"(d[2]), "+f"(d[3])                      \
        : "r"(a[0]), "r"(a[1]), "r"(a[2]), "r"(a[3]), "r"(b[0]), "r"(b[1]))

__device__ __forceinline__ void cp_async16(uint32_t smem_addr, const void* gptr) {
    asm volatile("cp.async.cg.shared.global [%0], [%1], 16;"
                 :: "r"(smem_addr), "l"(gptr) : "memory");
}
#define CP_COMMIT() asm volatile("cp.async.commit_group;" ::: "memory")
#define CP_WAIT1()  asm volatile("cp.async.wait_group 1;" ::: "memory")

// ---------------------------------------------------------------------------
// Kernel 0 (fused): pack A and W via smem staging (R16-verified layouts).
// Blocks [0, 1024): A tiles (kblk = bid & 63, mTile = bid >> 6).
// Blocks [1024, 4096): W tiles (idx = bid - 1024; nTile = idx % 48, kblk = idx / 48).
// ---------------------------------------------------------------------------
#define PACKA_BLOCKS 1024
#define PACKW_BLOCKS 3072

__global__ __launch_bounds__(256) void pack_aw_kernel(const float* __restrict__ A,
                                                      const float* __restrict__ W) {
    __shared__ uint32_t ps[4 * 1056];   // max of A (4*1032) and W (4*1056) layouts
    const int tid = threadIdx.x;

    if (blockIdx.x < PACKA_BLOCKS) {
        const int kblk  = blockIdx.x & 63;
        const int mTile = blockIdx.x >> 6;
        const float* Ab = A + (size_t)(mTile * 128) * DMODEL + kblk * 64;

#pragma unroll
        for (int it = 0; it < 8; it++) {
            int idx = tid + it * 256;
            int r  = idx >> 4;
            int c4 = (idx & 15) << 2;
            float4 v = *reinterpret_cast<const float4*>(Ab + (size_t)r * DMODEL + c4);
            int kt = c4 >> 4, kLoc = c4 & 15;
            int rb = r >> 4, r16 = r & 15;
            int reg = ((kLoc >= 8) ? 2 : 0) + ((r16 >= 8) ? 1 : 0);
            int lane0 = (r16 & 7) * 4 + ((kLoc >> 1) & 3);
            int base = kt * 1032 + rb * 128;
            ps[base + lane0 * 4 + reg]       = pack_h2(v.x, v.y);
            ps[base + (lane0 + 1) * 4 + reg] = pack_h2(v.z, v.w);
        }
        __syncthreads();

        uint32_t* dst = g_pa + ((size_t)(mTile * (DMODEL / 16) + kblk * 4)) * 1024;
#pragma unroll
        for (int kt = 0; kt < 4; kt++) {
            uint4 v = *reinterpret_cast<const uint4*>(&ps[kt * 1032 + tid * 4]);
            *reinterpret_cast<uint4*>(dst + kt * 1024 + tid * 4) = v;
        }
    } else {
        const int idx0  = blockIdx.x - PACKA_BLOCKS;
        const int nTile = idx0 % 48;
        const int kblk  = idx0 / 48;
        const float* Wb = W + (size_t)(kblk * 64) * QKVC + nTile * 128;

#pragma unroll
        for (int it = 0; it < 4; it++) {
            int idx = tid + it * 256;
            int kp   = idx >> 5;
            int lane = idx & 31;
            int k = kp * 2;
            const float* row = Wb + (size_t)k * QKVC + lane * 4;
            float4 vlo = *reinterpret_cast<const float4*>(row);
            float4 vhi = *reinterpret_cast<const float4*>(row + QKVC);

            int kt  = kp >> 3;
            int tg  = kp & 3;
            int reg = ((kp & 7) >= 4) ? 1 : 0;
            float lo[4] = {vlo.x, vlo.y, vlo.z, vlo.w};
            float hi[4] = {vhi.x, vhi.y, vhi.z, vhi.w};
#pragma unroll
            for (int j = 0; j < 4; j++) {
                int n = lane * 4 + j;
                int nblk = n >> 3, nn = n & 7;
                ps[kt * 1056 + nblk * 66 + (nn * 4 + tg) * 2 + reg] = pack_h2(lo[j], hi[j]);
            }
        }
        __syncthreads();

        uint32_t* dst = g_pb + ((size_t)(nTile * (DMODEL / 16) + kblk * 4)) * 1024;
        const int wid  = tid >> 5;
        const int lane = tid & 31;
#pragma unroll
        for (int wi = 0; wi < 8; wi++) {
            int c = wid * 8 + wi;
            int kt = c >> 4, nblk = c & 15;
            uint2 v = *reinterpret_cast<const uint2*>(&ps[kt * 1056 + nblk * 66 + lane * 2]);
            *reinterpret_cast<uint2*>(dst + kt * 1024 + nblk * 64 + lane * 2) = v;
        }
    }
}

// ---------------------------------------------------------------------------
// Kernel 1: QKV GEMM (R13-proven: fp16 m16n8k16, BK=64, 3 stages, 96KB,
// 256 threads / 8 warps 2x4, warp tile 64x32; fp16 epilogue).
// ---------------------------------------------------------------------------
__global__ __launch_bounds__(256, 2) void gemm_f16_kernel() {
    extern __shared__ __align__(16) uint32_t smem[];

    const int tid  = threadIdx.x;
    const int wid  = tid >> 5;
    const int lane = tid & 31;
    const int gid  = lane >> 2;
    const int tig  = lane & 3;
    const int wm   = wid >> 2;
    const int wn   = wid & 3;

    const uint32_t smem_base = (uint32_t)__cvta_generic_to_shared(smem);
    const uint32_t* pa = g_pa + (size_t)blockIdx.y * (DMODEL / 16) * 1024;
    const uint32_t* pb = g_pb + (size_t)blockIdx.x * (DMODEL / 16) * 1024;

    const int NCH = DMODEL / 64;

#define ISSUE(ch, s)                                                           \
    do {                                                                       \
        uint32_t sa = smem_base + (uint32_t)(s) * 32768;                       \
        const uint32_t* gA = pa + (size_t)(ch) * 4096 + tid * 4;               \
        const uint32_t* gB = pb + (size_t)(ch) * 4096 + tid * 4;               \
        cp_async16(sa + tid * 16,           gA);                               \
        cp_async16(sa + tid * 16 + 4096,    gA + 1024);                        \
        cp_async16(sa + tid * 16 + 8192,    gA + 2048);                        \
        cp_async16(sa + tid * 16 + 12288,   gA + 3072);                        \
        cp_async16(sa + 16384 + tid * 16,         gB);                         \
        cp_async16(sa + 16384 + tid * 16 + 4096,  gB + 1024);                  \
        cp_async16(sa + 16384 + tid * 16 + 8192,  gB + 2048);                  \
        cp_async16(sa + 16384 + tid * 16 + 12288, gB + 3072);                  \
    } while (0)

    float acc[4][4][4];
#pragma unroll
    for (int i = 0; i < 4; i++)
#pragma unroll
        for (int j = 0; j < 4; j++)
#pragma unroll
            for (int c = 0; c < 4; c++) acc[i][j][c] = 0.f;

    ISSUE(0, 0); CP_COMMIT();
    ISSUE(1, 1); CP_COMMIT();
    CP_WAIT1();
    __syncthreads();

    for (int ch = 0; ch < NCH; ch++) {
        if (ch + 2 < NCH) ISSUE(ch + 2, (ch + 2) % 3);
        CP_COMMIT();

        const uint32_t* St = smem + (size_t)(ch % 3) * 8192;

#pragma unroll
        for (int kt = 0; kt < 4; kt++) {
            const uint32_t* As = St + kt * 1024;
            const uint32_t* Bs = St + 4096 + kt * 1024;
            uint4 av[4];
            uint2 bv[4];
#pragma unroll
            for (int i = 0; i < 4; i++)
                av[i] = *reinterpret_cast<const uint4*>(
                    &As[((wm << 2) + i) * 128 + (lane << 2)]);
#pragma unroll
            for (int j = 0; j < 4; j++)
                bv[j] = *reinterpret_cast<const uint2*>(
                    &Bs[((wn << 2) + j) * 64 + (lane << 1)]);
#pragma unroll
            for (int i = 0; i < 4; i++)
#pragma unroll
                for (int j = 0; j < 4; j++)
                    MMA_F16(acc[i][j], (reinterpret_cast<uint32_t*>(&av[i])),
                            (reinterpret_cast<uint32_t*>(&bv[j])));
        }

        CP_WAIT1();
        __syncthreads();
    }

    uint32_t* C = g_qkvh + (size_t)blockIdx.y * 128 * (QKVC / 2) + blockIdx.x * 64;
#pragma unroll
    for (int i = 0; i < 4; i++) {
#pragma unroll
        for (int j = 0; j < 4; j++) {
            int r = wm * 64 + i * 16 + gid;
            int cp = wn * 16 + j * 4 + tig;
            C[(size_t)(r)     * (QKVC / 2) + cp] = pack_h2(acc[i][j][0], acc[i][j][1]);
            C[(size_t)(r + 8) * (QKVC / 2) + cp] = pack_h2(acc[i][j][2], acc[i][j][3]);
        }
    }
}

// ---------------------------------------------------------------------------
// Kernel 2 (fused): RoPE+pack Q/K, then pack V (block-range split). (R13)
// ---------------------------------------------------------------------------
#define ROPE_BLOCKS 10240
#define PACKV_BLOCKS 1024

__global__ __launch_bounds__(256) void rope_packqkv_kernel(const float* __restrict__ cosT,
                                                           const float* __restrict__ sinT) {
    if (blockIdx.x < ROPE_BLOCKS) {
        int idx = blockIdx.x * 256 + threadIdx.x;
        int j    = idx & 31;
        int head = (idx >> 5) % 40;
        int t    = idx / (32 * 40);
        int d0   = 2 * j;

        const uint32_t* p = g_qkvh + (size_t)t * (QKVC / 2) + head * 64;
        float2 x1 = unpack_h2(p[j]);
        float2 x2 = unpack_h2(p[32 + j]);
        float2 c  = *reinterpret_cast<const float2*>(cosT + t * HDIM + d0);
        float2 s  = *reinterpret_cast<const float2*>(sinT + t * HDIM + d0);

        float lo0 = x1.x * c.x - x2.x * s.x;
        float lo1 = x1.y * c.y - x2.y * s.y;
        float hi0 = x2.x * c.x + x1.x * s.x;
        float hi1 = x2.y * c.y + x1.y * s.y;

        int b = t >> 10;
        int tig = j & 3;
        int ktile = j >> 3;
        if (head < NH) {
            lo0 *= QSCALE; lo1 *= QSCALE; hi0 *= QSCALE; hi1 *= QSCALE;
            int qblk = (t & 1023) >> 7;
            int rLoc = t & 127, rb = rLoc >> 4, r16 = rLoc & 15;
            int reg = (((d0 & 15) >= 8) ? 2 : 0) + ((r16 >= 8) ? 1 : 0);
            int lane0 = (r16 & 7) * 4 + tig;
            uint32_t* dst = g_pq + ((size_t)((b * 8 + qblk) * 32 + head)) * 8192 + rb * 128;
            dst[ktile * 1024 + lane0 * 4 + reg]       = pack_h2(lo0, lo1);
            dst[(ktile + 4) * 1024 + lane0 * 4 + reg] = pack_h2(hi0, hi1);
        } else {
            int hkv = head - NH;
            int kvblk = (t & 1023) >> 6;
            int n = t & 63, nblk = n >> 3, nn = n & 7;
            int reg = ((d0 & 15) >= 8) ? 1 : 0;
            uint32_t* dst = g_pk + ((size_t)((b * 8 + hkv) * 16 + kvblk)) * 4096
                            + nblk * 64 + (nn * 4 + tig) * 2 + reg;
            dst[ktile * 512]       = pack_h2(lo0, lo1);
            dst[(ktile + 4) * 512] = pack_h2(hi0, hi1);
        }
    } else {
        int idx = (blockIdx.x - ROPE_BLOCKS) * 256 + threadIdx.x;
        int dq  = idx & 31;
        int hkv = (idx >> 5) & 7;
        int tp  = idx >> 8;
        int t   = tp * 2;
        int d0  = dq * 4;

        const uint32_t* Vg = g_qkvh + (size_t)t * (QKVC / 2) + (NH + NKV + hkv) * 64 + (d0 >> 1);
        uint2 vlo = *reinterpret_cast<const uint2*>(Vg);
        uint2 vhi = *reinterpret_cast<const uint2*>(Vg + (QKVC / 2));

        int b = t >> 10;
        int kvblk = (t & 1023) >> 6;
        int kc = t & 15;
        int tig = (kc >> 1) & 3;
        int reg = (kc >= 8) ? 1 : 0;
        int ktv = (t & 63) >> 4;
        uint32_t* dst = g_pv + ((size_t)((b * 8 + hkv) * 16 + kvblk)) * 4096 + ktv * 1024;

        uint32_t w[4];
        w[0] = __byte_perm(vlo.x, vhi.x, 0x5410);
        w[1] = __byte_perm(vlo.x, vhi.x, 0x7632);
        w[2] = __byte_perm(vlo.y, vhi.y, 0x5410);
        w[3] = __byte_perm(vlo.y, vhi.y, 0x7632);
#pragma unroll
        for (int jj = 0; jj < 4; jj++) {
            int d = d0 + jj;
            int nblk = d >> 3, nn = d & 7;
            dst[nblk * 64 + (nn * 4 + tig) * 2 + reg] = w[jj];
        }
    }
}

// ---------------------------------------------------------------------------
// Kernel 3: fp16 flash attention (R12/R13 core) with LONGEST-FIRST ordering.
// ---------------------------------------------------------------------------
#define ATTN_SMEM (3 * 8192 * 4)   // 98304

__global__ __launch_bounds__(256) void attn_tc_kernel(float* __restrict__ out) {
    extern __shared__ __align__(16) uint32_t sm[];
    const uint32_t smem_base = (uint32_t)__cvta_generic_to_shared(sm);

    const int tid  = threadIdx.x;
    const int wid  = tid >> 5;
    const int lane = tid & 31;
    const int gid  = lane >> 2;
    const int tig  = lane & 3;
    const int qrow = wid * 16;

    const int b   = blockIdx.y >> 5;
    const int h   = blockIdx.y & 31;
    const int kvh = h >> 2;
    const int qblk = (SEQ / 128 - 1) - blockIdx.x;   // longest-first
    const int q0  = qblk * 128;

    const uint32_t* qbase = g_pq + ((size_t)((b * 8 + qblk) * 32 + h)) * 8192;
    uint4 qa[8];
#pragma unroll
    for (int ks = 0; ks < 8; ks++)
        qa[ks] = *reinterpret_cast<const uint4*>(qbase + ks * 1024 + wid * 128 + lane * 4);

    const uint32_t* kbase = g_pk + ((size_t)((b * 8 + kvh) * 16)) * 4096;
    const uint32_t* vbase = g_pv + ((size_t)((b * 8 + kvh) * 16)) * 4096;

#define AISSUE(kt, s)                                                          \
    do {                                                                       \
        uint32_t sa = smem_base + (uint32_t)(s) * 32768;                       \
        const uint32_t* gK = kbase + (size_t)(kt) * 4096;                      \
        const uint32_t* gV = vbase + (size_t)(kt) * 4096;                      \
        _Pragma("unroll")                                                      \
        for (int i = 0; i < 4; i++) {                                          \
            int c = tid + i * 256;                                             \
            cp_async16(sa + c * 16,         gK + c * 4);                       \
            cp_async16(sa + 16384 + c * 16, gV + c * 4);                       \
        }                                                                      \
    } while (0)

    float m[2] = {-1e30f, -1e30f}, l[2] = {0.f, 0.f};
    float oacc[16][4];
#pragma unroll
    for (int nb = 0; nb < 16; nb++)
#pragma unroll
        for (int c = 0; c < 4; c++) oacc[nb][c] = 0.f;

    const int ktiles = 2 * (qblk + 1);
    AISSUE(0, 0); CP_COMMIT();
    AISSUE(1, 1); CP_COMMIT();

    for (int kt = 0; kt < ktiles; kt++) {
        const int kv0 = kt * 64;
        CP_WAIT1();
        __syncthreads();
        if (kt + 2 < ktiles) AISSUE(kt + 2, (kt + 2) % 3);
        CP_COMMIT();

        const uint32_t* Kst = sm + (size_t)(kt % 3) * 8192;
        const uint32_t* Vst = Kst + 4096;

        float sacc[8][4];
#pragma unroll
        for (int nb = 0; nb < 8; nb++)
#pragma unroll
            for (int c = 0; c < 4; c++) sacc[nb][c] = 0.f;

#pragma unroll
        for (int ks = 0; ks < 8; ks++) {
#pragma unroll
            for (int nb = 0; nb < 8; nb++) {
                uint2 bb = *reinterpret_cast<const uint2*>(
                    &Kst[ks * 512 + nb * 64 + (lane << 1)]);
                MMA_F16(sacc[nb], (reinterpret_cast<uint32_t*>(&qa[ks])),
                        (reinterpret_cast<uint32_t*>(&bb)));
            }
        }

        const int row0 = q0 + qrow + gid;
        const int row1 = row0 + 8;
        if (kv0 + 63 > row0) {
#pragma unroll
            for (int nb = 0; nb < 8; nb++) {
                int c0 = kv0 + nb * 8 + 2 * tig;
                if (c0 > row0)     sacc[nb][0] = -1e30f;
                if (c0 + 1 > row0) sacc[nb][1] = -1e30f;
                if (c0 > row1)     sacc[nb][2] = -1e30f;
                if (c0 + 1 > row1) sacc[nb][3] = -1e30f;
            }
        }

#pragma unroll
        for (int r = 0; r < 2; r++) {
            float rmax = -1e30f;
#pragma unroll
            for (int nb = 0; nb < 8; nb++)
                rmax = fmaxf(rmax, fmaxf(sacc[nb][2 * r], sacc[nb][2 * r + 1]));
            rmax = fmaxf(rmax, __shfl_xor_sync(0xffffffffu, rmax, 1));
            rmax = fmaxf(rmax, __shfl_xor_sync(0xffffffffu, rmax, 2));
            float nm = fmaxf(m[r], rmax);
            float corr = __expf(m[r] - nm);
            float rs = 0.f;
#pragma unroll
            for (int nb = 0; nb < 8; nb++) {
                float p0 = __expf(sacc[nb][2 * r]     - nm);
                float p1 = __expf(sacc[nb][2 * r + 1] - nm);
                sacc[nb][2 * r] = p0; sacc[nb][2 * r + 1] = p1;
                rs += p0 + p1;
            }
            rs += __shfl_xor_sync(0xffffffffu, rs, 1);
            rs += __shfl_xor_sync(0xffffffffu, rs, 2);
            m[r] = nm;
            l[r] = l[r] * corr + rs;
#pragma unroll
            for (int nb = 0; nb < 16; nb++) {
                oacc[nb][2 * r]     *= corr;
                oacc[nb][2 * r + 1] *= corr;
            }
        }

#pragma unroll
        for (int kb = 0; kb < 4; kb++) {
            uint32_t a[4];
            a[0] = pack_h2(sacc[2 * kb][0],     sacc[2 * kb][1]);
            a[1] = pack_h2(sacc[2 * kb][2],     sacc[2 * kb][3]);
            a[2] = pack_h2(sacc[2 * kb + 1][0], sacc[2 * kb + 1][1]);
            a[3] = pack_h2(sacc[2 * kb + 1][2], sacc[2 * kb + 1][3]);
#pragma unroll
            for (int nb = 0; nb < 16; nb++) {
                uint2 bb = *reinterpret_cast<const uint2*>(
                    &Vst[kb * 1024 + nb * 64 + (lane << 1)]);
                MMA_F16(oacc[nb], a, (reinterpret_cast<uint32_t*>(&bb)));
            }
        }
    }

    const float inv0 = 1.f / l[0];
    const float inv1 = 1.f / l[1];
    const int t0 = b * SEQ + q0 + qrow + gid;
#pragma unroll
    for (int nb = 0; nb < 16; nb++) {
        int c = nb * 8 + 2 * tig;
        float2 v0 = {oacc[nb][0] * inv0, oacc[nb][1] * inv0};
        float2 v1 = {oacc[nb][2] * inv1, oacc[nb][3] * inv1};
        *reinterpret_cast<float2*>(out + (size_t)t0 * (NH * HDIM) + h * HDIM + c) = v0;
        *reinterpret_cast<float2*>(out + (size_t)(t0 + 8) * (NH * HDIM) + h * HDIM + c) = v1;
    }
}

// ---------------------------------------------------------------------------
extern "C" void kernel_launch(void* const* d_in, const int* in_sizes, int n_in,
                              void* d_out, int out_size) {
    const float* hidden = (const float*)d_in[0];
    const float* w_qkv  = (const float*)d_in[1];
    const float* cosT   = (const float*)d_in[2];
    const float* sinT   = (const float*)d_in[3];
    float* out = (float*)d_out;

    cudaFuncSetAttribute(gemm_f16_kernel, cudaFuncAttributeMaxDynamicSharedMemorySize, 98304);
    cudaFuncSetAttribute(attn_tc_kernel, cudaFuncAttributeMaxDynamicSharedMemorySize, ATTN_SMEM);

    pack_aw_kernel<<<PACKA_BLOCKS + PACKW_BLOCKS, 256>>>(hidden, w_qkv);

    dim3 ggrid(QKVC / 128, T_TOK / 128);   // (48, 16)
    gemm_f16_kernel<<<ggrid, 256, 98304>>>();

    rope_packqkv_kernel<<<ROPE_BLOCKS + PACKV_BLOCKS, 256>>>(cosT, sinT);

    dim3 agrid(SEQ / 128, NBATCH * NH);    // (8, 64)
    attn_tc_kernel<<<agrid, 256, ATTN_SMEM>>>(out);
}